// round 13
// baseline (speedup 1.0000x reference)
#include <cuda_runtime.h>
#include <cuda_bf16.h>
#include <math.h>

#define OUT_G 12
#define V_G (OUT_G * OUT_G * OUT_G)   // 1728
#define MAXN 256
#define NB 16                          // spatial bins per dim
#define NBINS (NB * NB * NB)           // 4096
#define NWMAX 4                        // uint64 mask words (up to 256 rois)
#define DOM_LO (-12.0f)
#define DOM_HI (12.0f)
#define CELL ((DOM_HI - DOM_LO) / (float)NB)   // 1.5
#define TPB 256
#define MAXGRID 592

// __device__ globals (allocation-free rule)
__device__ int g_count[MAXN * V_G];
__device__ unsigned long long g_mask[NBINS * NWMAX];
__device__ unsigned g_bar_count;   // barrier arrivals (always returns to 0)
__device__ unsigned g_bar_gen;     // barrier generation (monotonic, ok to persist)

__device__ __forceinline__ unsigned enc_f(float f) {
    unsigned u = __float_as_uint(f);
    return (u & 0x80000000u) ? ~u : (u | 0x80000000u);
}
__device__ __forceinline__ float dec_f(unsigned u) {
    return (u & 0x80000000u) ? __uint_as_float(u & 0x7FFFFFFFu) : __uint_as_float(~u);
}

// Software grid barrier. Safe because the grid is sized to be fully
// co-resident (occupancy query on host). Gen counter is monotonic across
// graph replays; count always drains back to 0.
__device__ __forceinline__ void grid_barrier() {
    __syncthreads();
    if (threadIdx.x == 0) {
        __threadfence();
        unsigned my = atomicAdd(&g_bar_gen, 0u);      // current generation
        unsigned old = atomicAdd(&g_bar_count, 1u);
        if (old == gridDim.x - 1u) {
            atomicExch(&g_bar_count, 0u);
            __threadfence();
            atomicAdd(&g_bar_gen, 1u);                // release
        } else {
            while (atomicAdd(&g_bar_gen, 0u) == my) __nanosleep(64);
        }
        __threadfence();
    }
    __syncthreads();
}

// ---------------------------------------------------------------------------
// Fused persistent kernel: setup -> barrier -> points -> barrier -> finalize
// ---------------------------------------------------------------------------
__global__ void __launch_bounds__(TPB)
roi_fused_kernel(const float* __restrict__ rois,
                 const float* __restrict__ pts,
                 const float* __restrict__ feat,
                 const int* __restrict__ mode_p,
                 float* __restrict__ out,
                 int N, int P, int C, long total_out) {
    __shared__ float s_roi[MAXN * 12];   // cx,cy,czc,cosa,sina,hx,hy,hz,vx,vy,vz,rad2

    int tid = blockIdx.x * blockDim.x + threadIdx.x;
    int nth = gridDim.x * blockDim.x;

    // ---- Phase A: roi params (per block, persists in smem), zero out+counts,
    // ----          ballot-build bin masks (conservative circumradius AABB).
    for (int r = threadIdx.x; r < N; r += blockDim.x) {
        float cx = __ldg(&rois[7 * r + 0]);
        float cy = __ldg(&rois[7 * r + 1]);
        float czb = __ldg(&rois[7 * r + 2]);
        float dx = __ldg(&rois[7 * r + 3]);
        float dy = __ldg(&rois[7 * r + 4]);
        float dz = __ldg(&rois[7 * r + 5]);
        float rz = __ldg(&rois[7 * r + 6]);
        float czc = czb + dz * 0.5f;
        float cosa = cosf(-rz);
        float sina = sinf(-rz);
        float hx = dx * 0.5f, hy = dy * 0.5f, hz = dz * 0.5f;
        float* R = &s_roi[r * 12];
        R[0] = cx; R[1] = cy; R[2] = czc; R[3] = cosa; R[4] = sina;
        R[5] = hx; R[6] = hy; R[7] = hz;
        R[8] = dx / (float)OUT_G; R[9] = dy / (float)OUT_G; R[10] = dz / (float)OUT_G;
        R[11] = hx * hx + hy * hy;
    }
    __syncthreads();

    // zero output (atomics land directly in out during phase B)
    long nv4 = total_out >> 2;
    float4 z4 = make_float4(0.f, 0.f, 0.f, 0.f);
    float4* o4 = reinterpret_cast<float4*>(out);
    for (long i = tid; i < nv4; i += nth) o4[i] = z4;
    for (long i = (nv4 << 2) + tid; i < total_out; i += nth) out[i] = 0.0f;

    long nc = (long)N * V_G;
    for (long i = tid; i < nc; i += nth) g_count[i] = 0;

    // ballot mask build: one lane per (bin, roi) AABB test
    {
        int lane = threadIdx.x & 31;
        int gwarp = tid >> 5;
        int nwarps = nth >> 5;
        int nw32 = (N + 31) >> 5;
        int pairs = NBINS * nw32;
        unsigned* mask32 = reinterpret_cast<unsigned*>(g_mask);

        for (int idx = gwarp; idx < pairs; idx += nwarps) {
            int b = idx / nw32;
            int w32 = idx - b * nw32;
            int r = (w32 << 5) + lane;

            int bx = b & (NB - 1), by = (b >> 4) & (NB - 1), bz = b >> 8;
            float x0 = (bx == 0)      ? -3e38f : DOM_LO + bx * CELL;
            float x1 = (bx == NB - 1) ?  3e38f : DOM_LO + (bx + 1) * CELL;
            float y0 = (by == 0)      ? -3e38f : DOM_LO + by * CELL;
            float y1 = (by == NB - 1) ?  3e38f : DOM_LO + (by + 1) * CELL;
            float z0 = (bz == 0)      ? -3e38f : DOM_LO + bz * CELL;
            float z1 = (bz == NB - 1) ?  3e38f : DOM_LO + (bz + 1) * CELL;

            bool ov = false;
            if (r < N) {
                const float* R = &s_roi[r * 12];
                float rad = sqrtf(R[11]);
                ov = (R[0] - rad <= x1) & (R[0] + rad >= x0) &
                     (R[1] - rad <= y1) & (R[1] + rad >= y0) &
                     (R[2] - R[7] <= z1) & (R[2] + R[7] >= z0);
            }
            unsigned m = __ballot_sync(0xFFFFFFFFu, ov);
            if (lane == 0) {
                mask32[b * (NWMAX * 2) + w32] = m;
                if (w32 == 0)
                    for (int w = nw32; w < NWMAX * 2; w++)
                        mask32[b * (NWMAX * 2) + w] = 0u;
            }
        }
    }

    grid_barrier();

    // ---- Phase B: points pass (grid-stride), atomics into out.
    {
        int mode = __ldg(mode_p);
        const float invcell = 1.0f / CELL;
        int nw = (N + 63) >> 6;

        for (int p = tid; p < P; p += nth) {
            float px = __ldg(&pts[3 * p + 0]);
            float py = __ldg(&pts[3 * p + 1]);
            float pz = __ldg(&pts[3 * p + 2]);

            int bx = min(NB - 1, max(0, (int)((px - DOM_LO) * invcell)));
            int by = min(NB - 1, max(0, (int)((py - DOM_LO) * invcell)));
            int bz = min(NB - 1, max(0, (int)((pz - DOM_LO) * invcell)));
            int bin = (bz * NB + by) * NB + bx;

            for (int w = 0; w < nw; w++) {
                unsigned long long m = __ldg(&g_mask[(long)bin * NWMAX + w]);
                while (m) {
                    int bit = __ffsll((long long)m) - 1;
                    m &= m - 1;
                    int r = (w << 6) + bit;
                    const float* R = &s_roi[r * 12];

                    float lz = pz - R[2];
                    float hz = R[7];
                    if (fabsf(lz) > hz) continue;
                    float sx = px - R[0];
                    float sy = py - R[1];
                    if (sx * sx + sy * sy > R[11]) continue;
                    float cosa = R[3], sina = R[4];
                    float lx = sx * cosa - sy * sina;
                    float ly = sx * sina + sy * cosa;
                    float hx = R[5], hy = R[6];
                    if (fabsf(lx) >= hx) continue;
                    if (fabsf(ly) >= hy) continue;

                    int xi = min(max((int)floorf((lx + hx) / R[8]), 0), OUT_G - 1);
                    int yi = min(max((int)floorf((ly + hy) / R[9]), 0), OUT_G - 1);
                    int zi = min(max((int)floorf((lz + hz) / R[10]), 0), OUT_G - 1);
                    int rv = r * V_G + (xi * OUT_G + yi) * OUT_G + zi;

                    atomicAdd(&g_count[rv], 1);     // fire-and-forget -> REDG
                    long base = (long)rv * C;

                    if ((C & 3) == 0) {
                        const float4* fp4 = (const float4*)(feat + (long)p * C);
                        if (mode == 0) {
                            unsigned* o = reinterpret_cast<unsigned*>(out) + base;
                            for (int c4 = 0; c4 < (C >> 2); c4++) {
                                float4 f = __ldg(fp4 + c4);
                                atomicMax(o + 4 * c4 + 0, enc_f(f.x));
                                atomicMax(o + 4 * c4 + 1, enc_f(f.y));
                                atomicMax(o + 4 * c4 + 2, enc_f(f.z));
                                atomicMax(o + 4 * c4 + 3, enc_f(f.w));
                            }
                        } else {
                            float* o = out + base;
                            for (int c4 = 0; c4 < (C >> 2); c4++) {
                                float4 f = __ldg(fp4 + c4);
                                atomicAdd(o + 4 * c4 + 0, f.x);
                                atomicAdd(o + 4 * c4 + 1, f.y);
                                atomicAdd(o + 4 * c4 + 2, f.z);
                                atomicAdd(o + 4 * c4 + 3, f.w);
                            }
                        }
                    } else {
                        const float* fp = feat + (long)p * C;
                        if (mode == 0) {
                            unsigned* o = reinterpret_cast<unsigned*>(out) + base;
                            for (int c = 0; c < C; c++) atomicMax(o + c, enc_f(__ldg(fp + c)));
                        } else {
                            float* o = out + base;
                            for (int c = 0; c < C; c++) atomicAdd(o + c, __ldg(fp + c));
                        }
                    }
                }
            }
        }
    }

    grid_barrier();

    // ---- Phase C: finalize occupied voxels only. Empty voxels already 0.0f.
    {
        int mode = __ldg(mode_p);
        int NV = N * V_G;
        for (int v = tid; v < NV; v += nth) {
            int cnt = g_count[v];
            if (cnt <= 0) continue;
            long base = (long)v * C;
            if ((C & 3) == 0) {
                uint4* o4v = reinterpret_cast<uint4*>(reinterpret_cast<unsigned*>(out) + base);
                if (mode == 0) {
                    for (int c4 = 0; c4 < (C >> 2); c4++) {
                        uint4 s = o4v[c4];
                        s.x = __float_as_uint(dec_f(s.x));
                        s.y = __float_as_uint(dec_f(s.y));
                        s.z = __float_as_uint(dec_f(s.z));
                        s.w = __float_as_uint(dec_f(s.w));
                        o4v[c4] = s;
                    }
                } else {
                    float inv = 1.0f / (float)cnt;
                    float4* f4v = reinterpret_cast<float4*>(out + base);
                    for (int c4 = 0; c4 < (C >> 2); c4++) {
                        float4 f = f4v[c4];
                        f.x *= inv; f.y *= inv; f.z *= inv; f.w *= inv;
                        f4v[c4] = f;
                    }
                }
            } else {
                if (mode == 0) {
                    unsigned* o = reinterpret_cast<unsigned*>(out) + base;
                    for (int c = 0; c < C; c++) o[c] = __float_as_uint(dec_f(o[c]));
                } else {
                    float inv = 1.0f / (float)cnt;
                    float* o = out + base;
                    for (int c = 0; c < C; c++) o[c] *= inv;
                }
            }
        }
    }
}

extern "C" void kernel_launch(void* const* d_in, const int* in_sizes, int n_in,
                              void* d_out, int out_size) {
    const float* rois = (const float*)d_in[0];
    const float* pts = (const float*)d_in[1];
    const float* feat = (const float*)d_in[2];
    const int* mode_p = (const int*)d_in[3];
    float* out = (float*)d_out;

    int N = in_sizes[0] / 7;          // 64
    int P = in_sizes[1] / 3;          // 100000
    int C = in_sizes[2] / P;          // 16
    long total_out = (long)out_size;  // N*V*C

    // Size grid for guaranteed co-residency (software grid barrier inside).
    int smCount = 0, perSM = 0;
    cudaDeviceGetAttribute(&smCount, cudaDevAttrMultiProcessorCount, 0);
    cudaOccupancyMaxActiveBlocksPerMultiprocessor(&perSM, roi_fused_kernel, TPB, 0);
    if (smCount <= 0) smCount = 148;
    if (perSM <= 0) perSM = 1;
    int grid = smCount * perSM;
    if (grid > MAXGRID) grid = MAXGRID;

    roi_fused_kernel<<<grid, TPB>>>(rois, pts, feat, mode_p, out, N, P, C, total_out);
}